// round 15
// baseline (speedup 1.0000x reference)
#include <cuda_runtime.h>
#include <cuda_fp16.h>
#include <cstdint>

#define N_POL   100000
#define N_TICK  20000
#define NN      (N_POL + N_TICK)   // 120000
#define NPAD    120064
#define NB1     469
#define NT      938                // m-tiles of 128
#define E_EDGES 1000000
#define POL_FEAT 7
#define EMB     128
#define HID     256
#define OUTD    128

// ---------------- scratch (static device globals; no allocation) ----------------
__device__ uint16_t g_xh[(size_t)NPAD * EMB];     // x fp16
__device__ uint16_t g_a1h[(size_t)NPAD * EMB];    // agg1 fp16
__device__ uint16_t g_hh[(size_t)NPAD * HID];     // h fp16
__device__ uint16_t g_yh[(size_t)NPAD * EMB];     // y = h@W2rel fp16
__device__ uint16_t g_w1h[256 * 256];             // [n][k] fp16
__device__ uint16_t g_w2h[256 * 256];
// CSR structures
__device__ int  g_cnt[NPAD];
__device__ int  g_off[NPAD];
__device__ int  g_cur[NPAD];
// decoupled-lookback descriptor: bits[62:64)=state (0 empty,1 partial,2 inclusive),
// bits[0:32)=sum. Single 8-byte word => flag+value read atomically.
__device__ unsigned long long g_desc[NB1];
__device__ int2 g_edge[E_EDGES];    // {src, weight_bits} sorted by dst

// ---------------- helpers ----------------
__device__ __forceinline__ uint32_t smem_u32(const void* p) {
    uint32_t a;
    asm("{ .reg .u64 t; cvta.to.shared.u64 t, %1; cvt.u32.u64 %0, t; }" : "=r"(a) : "l"(p));
    return a;
}
#define LDSM_X4(r0, r1, r2, r3, addr) \
    asm volatile("ldmatrix.sync.aligned.m8n8.x4.shared.b16 {%0,%1,%2,%3}, [%4];" \
        : "=r"(r0), "=r"(r1), "=r"(r2), "=r"(r3) : "r"(addr))
#define MMA_F16(c, a, b0, b1) \
    asm volatile("mma.sync.aligned.m16n8k16.row.col.f32.f16.f16.f32 " \
        "{%0,%1,%2,%3}, {%4,%5,%6,%7}, {%8,%9}, {%0,%1,%2,%3};" \
        : "+f"((c)[0]), "+f"((c)[1]), "+f"((c)[2]), "+f"((c)[3]) \
        : "r"((a)[0]), "r"((a)[1]), "r"((a)[2]), "r"((a)[3]), "r"(b0), "r"(b1))
#define CP16(dst, src) \
    asm volatile("cp.async.cg.shared.global [%0], [%1], 16;" :: "r"(dst), "l"(src))
#define CP_COMMIT() asm volatile("cp.async.commit_group;" ::: "memory")
template <int N> __device__ __forceinline__ void cp_wait() {
    asm volatile("cp.async.wait_group %0;" :: "n"(N) : "memory");
}
__device__ __forceinline__ uint32_t pack_h2(float a, float b) {
    __half2 t = __floats2half2_rn(a, b);
    return *reinterpret_cast<uint32_t*>(&t);
}
__device__ __forceinline__ uint2 pack_h4(float4 v) {
    return make_uint2(pack_h2(v.x, v.y), pack_h2(v.z, v.w));
}
__device__ __forceinline__ float4 unpack_h4(uint2 p) {
    float2 a = __half22float2(*reinterpret_cast<__half2*>(&p.x));
    float2 b = __half22float2(*reinterpret_cast<__half2*>(&p.y));
    return make_float4(a.x, a.y, b.x, b.y);
}

// ---------------- fused prep: build_x fp16 | weight fp16 + zero cnt/desc ----------------
#define BX_BLOCKS 15000   // NN*32/256
__global__ __launch_bounds__(256)
void prep_kernel(const float* __restrict__ pol, const int* __restrict__ sid,
                 const float* __restrict__ Wp, const float* __restrict__ bp,
                 const float* __restrict__ semb, const float* __restrict__ tick,
                 const float* __restrict__ W1rel, const float* __restrict__ W1root,
                 const float* __restrict__ W2rel, const float* __restrict__ W2root)
{
    if (blockIdx.x < BX_BLOCKS) {
        int t = blockIdx.x * 256 + threadIdx.x;
        int node = t >> 5;
        int c4 = (t & 31) * 4;
        if (node >= NN) return;
        float4 r;
        if (node < N_POL) {
            float4 acc = *(const float4*)(bp + c4);
            #pragma unroll
            for (int k = 0; k < POL_FEAT; k++) {
                float f = __ldg(pol + node * POL_FEAT + k);
                float4 w = *(const float4*)(Wp + k * EMB + c4);
                acc.x += f * w.x; acc.y += f * w.y; acc.z += f * w.z; acc.w += f * w.w;
            }
            int s = sid[node];
            float4 se = *(const float4*)(semb + (size_t)s * EMB + c4);
            r.x = fmaxf(acc.x, 0.f) + se.x;
            r.y = fmaxf(acc.y, 0.f) + se.y;
            r.z = fmaxf(acc.z, 0.f) + se.z;
            r.w = fmaxf(acc.w, 0.f) + se.w;
        } else {
            r = *(const float4*)(tick + (size_t)(node - N_POL) * EMB + c4);
        }
        *(uint2*)&g_xh[(size_t)node * EMB + c4] = pack_h4(r);
    } else {
        int idx = (blockIdx.x - BX_BLOCKS) * 256 + threadIdx.x;   // 0..131071
        if (idx < NPAD / 4) ((int4*)g_cnt)[idx] = make_int4(0, 0, 0, 0);
        if (idx < NB1) g_desc[idx] = 0ull;
        int which = idx >> 16;
        int e = idx & 65535;
        int n = e >> 8, k = e & 255;
        float v;
        if (which == 0) v = (k < 128) ? W1rel[k * 256 + n] : W1root[(k - 128) * 256 + n];
        else            v = (n < 128) ? W2rel[k * 128 + n] : W2root[k * 128 + (n - 128)];
        __half bh = __float2half(v);
        uint16_t h = *reinterpret_cast<uint16_t*>(&bh);
        if (which == 0) g_w1h[e] = h;
        else            g_w2h[e] = h;
    }
}

// ---------------- CSR build ----------------
__global__ __launch_bounds__(256)
void hist_kernel(const int* __restrict__ ei)
{
    int e = blockIdx.x * 256 + threadIdx.x;
    if (e < E_EDGES) atomicAdd(&g_cnt[ei[E_EDGES + e]], 1);
}

// single-kernel scan: local exclusive scan + decoupled look-back (packed 64-bit descriptors)
__global__ __launch_bounds__(256)
void scan_kernel()
{
    __shared__ int s[256];
    __shared__ int s_base;
    int tid = threadIdx.x;
    int bid = blockIdx.x;
    int idx = bid * 256 + tid;
    int v = g_cnt[idx];
    s[tid] = v;
    __syncthreads();
    #pragma unroll
    for (int d = 1; d < 256; d <<= 1) {
        int t = (tid >= d) ? s[tid - d] : 0;
        __syncthreads();
        s[tid] += t;
        __syncthreads();
    }
    int local_excl = s[tid] - v;
    int block_total = s[255];

    if (tid == 0) {
        volatile unsigned long long* desc = (volatile unsigned long long*)g_desc;
        if (bid == 0) {
            desc[0] = (2ull << 62) | (unsigned int)block_total;
            s_base = 0;
        } else {
            desc[bid] = (1ull << 62) | (unsigned int)block_total;   // partial
            int base = 0;
            int j = bid - 1;
            while (true) {
                unsigned long long d;
                do { d = desc[j]; } while ((d >> 62) == 0);
                base += (int)(unsigned int)(d & 0xffffffffull);
                if ((d >> 62) == 2) break;                          // inclusive found
                j--;
            }
            desc[bid] = (2ull << 62) | (unsigned int)(base + block_total);
            s_base = base;
        }
    }
    __syncthreads();
    int o = s_base + local_excl;
    g_off[idx] = o;
    g_cur[idx] = o;
}

__global__ __launch_bounds__(256)
void place_kernel(const int* __restrict__ ei, const float* __restrict__ ew)
{
    int e = blockIdx.x * 256 + threadIdx.x;
    if (e >= E_EDGES) return;
    int s = ei[e];
    int d = ei[E_EDGES + e];
    float w = ew[e];
    int pos = atomicAdd(&g_cur[d], 1);
    g_edge[pos] = make_int2(s, __float_as_int(w));
}

// ---------------- gather1: a1 = fp16( sum_e w * x[src] ) ----------------
__global__ __launch_bounds__(256)
void gather1_kernel()
{
    int t = blockIdx.x * blockDim.x + threadIdx.x;
    int node = t >> 5;
    int c4 = (t & 31) * 4;
    if (node >= NN) return;

    int cnt = __ldg(&g_cnt[node]);
    int off = __ldg(&g_off[node]);

    float4 acc = make_float4(0.f, 0.f, 0.f, 0.f);
    int i = 0;
    for (; i + 1 < cnt; i += 2) {
        int2 e0 = __ldg(&g_edge[off + i]);
        int2 e1 = __ldg(&g_edge[off + i + 1]);
        float4 v0 = unpack_h4(*(const uint2*)&g_xh[(size_t)e0.x * EMB + c4]);
        float4 v1 = unpack_h4(*(const uint2*)&g_xh[(size_t)e1.x * EMB + c4]);
        float w0 = __int_as_float(e0.y);
        float w1 = __int_as_float(e1.y);
        acc.x += w0 * v0.x + w1 * v1.x;
        acc.y += w0 * v0.y + w1 * v1.y;
        acc.z += w0 * v0.z + w1 * v1.z;
        acc.w += w0 * v0.w + w1 * v1.w;
    }
    if (i < cnt) {
        int2 e0 = __ldg(&g_edge[off + i]);
        float4 v0 = unpack_h4(*(const uint2*)&g_xh[(size_t)e0.x * EMB + c4]);
        float w0 = __int_as_float(e0.y);
        acc.x += w0 * v0.x; acc.y += w0 * v0.y;
        acc.z += w0 * v0.z; acc.w += w0 * v0.w;
    }

    *(uint2*)&g_a1h[(size_t)node * EMB + c4] = pack_h4(acc);
}

// ---------------- gather2: out += sum_e w * y[src]  (y fp16) ----------------
__global__ __launch_bounds__(256)
void gather2_kernel(float* __restrict__ out)
{
    int t = blockIdx.x * blockDim.x + threadIdx.x;
    int node = t >> 5;
    int c4 = (t & 31) * 4;
    if (node >= NN) return;

    int cnt = __ldg(&g_cnt[node]);
    if (cnt == 0) return;
    int off = __ldg(&g_off[node]);

    float4 acc = make_float4(0.f, 0.f, 0.f, 0.f);
    int i = 0;
    for (; i + 1 < cnt; i += 2) {
        int2 e0 = __ldg(&g_edge[off + i]);
        int2 e1 = __ldg(&g_edge[off + i + 1]);
        float4 v0 = unpack_h4(*(const uint2*)&g_yh[(size_t)e0.x * EMB + c4]);
        float4 v1 = unpack_h4(*(const uint2*)&g_yh[(size_t)e1.x * EMB + c4]);
        float w0 = __int_as_float(e0.y);
        float w1 = __int_as_float(e1.y);
        acc.x += w0 * v0.x + w1 * v1.x;
        acc.y += w0 * v0.y + w1 * v1.y;
        acc.z += w0 * v0.z + w1 * v1.z;
        acc.w += w0 * v0.w + w1 * v1.w;
    }
    if (i < cnt) {
        int2 e0 = __ldg(&g_edge[off + i]);
        float4 v0 = unpack_h4(*(const uint2*)&g_yh[(size_t)e0.x * EMB + c4]);
        float w0 = __int_as_float(e0.y);
        acc.x += w0 * v0.x; acc.y += w0 * v0.y;
        acc.z += w0 * v0.z; acc.w += w0 * v0.w;
    }

    float* o = out + (size_t)node * EMB + c4;
    float4 cur = *(float4*)o;
    cur.x += acc.x; cur.y += acc.y; cur.z += acc.z; cur.w += acc.w;
    *(float4*)o = cur;
}

// =========== persistent-B HMMA fp16 GEMM, BK=64, continuous cross-tile pipeline ===========
// MODE 1: A = [a1|x] fp16, writes g_hh = fp16(relu(acc + b1))
// MODE 2: A = h fp16, writes y fp16 | out f32 (+b2)
#define A_KSTR  72                        // 64 + 8 pad fp16
#define A_PLANE (128 * A_KSTR * 2)        // 18432
#define B_KSTR  264
#define B_PLANE (64 * B_KSTR * 2)         // 33792
#define SM_A    (B_PLANE)
#define SMTOT   (SM_A + 2 * A_PLANE)      // 70656
#define NSLOT   111                       // 444 CTAs / 4 quarters (3 per SM)

template <int MODE>
__global__ __launch_bounds__(256, 3)
void gcn_gemm_mma(const float* __restrict__ bias, float* __restrict__ dout)
{
    extern __shared__ char smem[];
    const uint32_t sb = smem_u32(smem);

    const int tid  = threadIdx.x;
    const int lane = tid & 31;
    const int wid  = tid >> 5;
    const int wm   = wid >> 1;
    const int wn   = wid & 1;
    const int q    = blockIdx.x & 3;
    const int slot = blockIdx.x >> 2;

    const uint16_t* wh = (MODE == 1) ? g_w1h : g_w2h;

    // ---- load B quarter once: [64 n][256 k]
    #pragma unroll
    for (int i = 0; i < 8; i++) {
        int c = i * 256 + tid;
        int row = c >> 5;
        int col = c & 31;
        const uint16_t* src = wh + (size_t)(q * 64 + row) * 256 + col * 8;
        uint32_t dst = sb + (uint32_t)(row * B_KSTR + col * 8) * 2;
        CP16(dst, src);
    }
    CP_COMMIT();
    cp_wait<0>();
    __syncthreads();

    auto issue = [&](int m0, int kc, int st) {
        const uint16_t* ah;
        int astr, kb;
        if (MODE == 1) {
            ah = (kc < 2) ? g_a1h : g_xh;
            astr = 128; kb = (kc & 1) * 64;
        } else {
            ah = g_hh; astr = 256; kb = kc * 64;
        }
        uint32_t base = sb + SM_A + st * A_PLANE;
        #pragma unroll
        for (int i = 0; i < 4; i++) {
            int c = i * 256 + tid;
            int row = c >> 3;
            int col = c & 7;
            const uint16_t* src = ah + (size_t)(m0 + row) * astr + kb + col * 8;
            uint32_t dst = base + (uint32_t)(row * A_KSTR + col * 8) * 2;
            CP16(dst, src);
        }
        CP_COMMIT();
    };

    const int rA = (lane & 7) + ((lane >> 3) & 1) * 8;
    const int kA = (lane >> 4) * 8;
    const int rB = (lane & 7) + ((lane >> 4) & 1) * 8;
    const int kB = ((lane >> 3) & 1) * 8;
    const int rr = lane >> 2;
    const int cc = (lane & 3) * 2;

    if (slot >= NT) return;
    issue(slot * 128, 0, 0);
    int st = 0;

    for (int t = slot; t < NT; t += NSLOT) {
        const int m0 = t * 128;

        float acc[2][4][4];
        #pragma unroll
        for (int i = 0; i < 2; i++)
            #pragma unroll
            for (int j = 0; j < 4; j++)
                #pragma unroll
                for (int p = 0; p < 4; p++) acc[i][j][p] = 0.f;

        for (int kc = 0; kc < 4; kc++) {
            int nkc = kc + 1, ntile = t;
            if (nkc == 4) { nkc = 0; ntile = t + NSLOT; }
            if (ntile < NT) { issue(ntile * 128, nkc, st ^ 1); cp_wait<1>(); }
            else            { cp_wait<0>(); }
            __syncthreads();

            uint32_t uA = sb + SM_A + st * A_PLANE;

            #pragma unroll
            for (int ks = 0; ks < 4; ks++) {
                uint32_t ah[2][4];
                #pragma unroll
                for (int mt = 0; mt < 2; mt++) {
                    uint32_t off = ((uint32_t)((wm * 32 + mt * 16 + rA) * A_KSTR + ks * 16 + kA)) * 2;
                    LDSM_X4(ah[mt][0], ah[mt][1], ah[mt][2], ah[mt][3], uA + off);
                }
                #pragma unroll
                for (int np = 0; np < 2; np++) {
                    uint32_t boff = ((uint32_t)((wn * 32 + np * 16 + rB) * B_KSTR + kc * 64 + ks * 16 + kB)) * 2;
                    uint32_t bh[4];
                    LDSM_X4(bh[0], bh[1], bh[2], bh[3], sb + boff);
                    #pragma unroll
                    for (int mt = 0; mt < 2; mt++) {
                        MMA_F16(acc[mt][np * 2 + 0], ah[mt], bh[0], bh[1]);
                        MMA_F16(acc[mt][np * 2 + 1], ah[mt], bh[2], bh[3]);
                    }
                }
            }
            __syncthreads();
            st ^= 1;
        }

        #pragma unroll
        for (int mt = 0; mt < 2; mt++) {
            #pragma unroll
            for (int j = 0; j < 4; j++) {
                int gm = m0 + wm * 32 + mt * 16 + rr;
                int gN = q * 64 + wn * 32 + j * 8 + cc;
                if (MODE == 1) {
                    float2 bv = *(const float2*)(bias + gN);
                    float v00 = fmaxf(acc[mt][j][0] + bv.x, 0.f);
                    float v01 = fmaxf(acc[mt][j][1] + bv.y, 0.f);
                    float v10 = fmaxf(acc[mt][j][2] + bv.x, 0.f);
                    float v11 = fmaxf(acc[mt][j][3] + bv.y, 0.f);
                    *(uint32_t*)&g_hh[(size_t)gm * 256 + gN]       = pack_h2(v00, v01);
                    *(uint32_t*)&g_hh[(size_t)(gm + 8) * 256 + gN] = pack_h2(v10, v11);
                } else if (gN < 128) {
                    *(uint32_t*)&g_yh[(size_t)gm * 128 + gN]       = pack_h2(acc[mt][j][0], acc[mt][j][1]);
                    *(uint32_t*)&g_yh[(size_t)(gm + 8) * 128 + gN] = pack_h2(acc[mt][j][2], acc[mt][j][3]);
                } else {
                    int nc = gN - 128;
                    float2 bv = *(const float2*)(bias + nc);
                    if (gm < NN)
                        *(float2*)(dout + (size_t)gm * 128 + nc) =
                            make_float2(acc[mt][j][0] + bv.x, acc[mt][j][1] + bv.y);
                    if (gm + 8 < NN)
                        *(float2*)(dout + (size_t)(gm + 8) * 128 + nc) =
                            make_float2(acc[mt][j][2] + bv.x, acc[mt][j][3] + bv.y);
                }
            }
        }
    }
}

// ---------------- launch ----------------
extern "C" void kernel_launch(void* const* d_in, const int* in_sizes, int n_in,
                              void* d_out, int out_size)
{
    const float* pol   = (const float*)d_in[0];
    const int*   sid   = (const int*)  d_in[1];
    const int*   ei    = (const int*)  d_in[2];
    const float* ew    = (const float*)d_in[3];
    const float* Wp    = (const float*)d_in[4];
    const float* bp    = (const float*)d_in[5];
    const float* semb  = (const float*)d_in[6];
    const float* tick  = (const float*)d_in[7];
    const float* W1rel = (const float*)d_in[8];
    const float* b1    = (const float*)d_in[9];
    const float* W1root= (const float*)d_in[10];
    const float* W2rel = (const float*)d_in[11];
    const float* b2    = (const float*)d_in[12];
    const float* W2root= (const float*)d_in[13];
    float* out = (float*)d_out;

    cudaFuncSetAttribute(gcn_gemm_mma<1>, cudaFuncAttributeMaxDynamicSharedMemorySize, SMTOT);
    cudaFuncSetAttribute(gcn_gemm_mma<2>, cudaFuncAttributeMaxDynamicSharedMemorySize, SMTOT);

    // 0) fused prep: x fp16 | W fp16 + zero cnt/desc
    prep_kernel<<<BX_BLOCKS + 512, 256>>>(pol, sid, Wp, bp, semb, tick,
                                          W1rel, W1root, W2rel, W2root);
    // 1) CSR build
    hist_kernel<<<(E_EDGES + 255) / 256, 256>>>(ei);
    scan_kernel<<<NB1, 256>>>();
    place_kernel<<<(E_EDGES + 255) / 256, 256>>>(ei, ew);
    // 2) gather1
    gather1_kernel<<<NN * 32 / 256, 256>>>();
    // 3) GEMM1
    gcn_gemm_mma<1><<<4 * NSLOT, 256, SMTOT>>>(b1, nullptr);
    // 4) GEMM2
    gcn_gemm_mma<2><<<4 * NSLOT, 256, SMTOT>>>(b2, out);
    // 5) gather2
    gather2_kernel<<<NN * 32 / 256, 256>>>(out);
}

// round 16
// speedup vs baseline: 1.1313x; 1.1313x over previous
#include <cuda_runtime.h>
#include <cuda_fp16.h>
#include <cstdint>

#define N_POL   100000
#define N_TICK  20000
#define NN      (N_POL + N_TICK)   // 120000
#define NPAD    120064
#define NB1     469
#define NT      938                // m-tiles of 128
#define E_EDGES 1000000
#define POL_FEAT 7
#define EMB     128
#define HID     256
#define OUTD    128

// ---------------- scratch (static device globals; no allocation) ----------------
__device__ uint16_t g_xh[(size_t)NPAD * EMB];     // x fp16
__device__ uint16_t g_a1h[(size_t)NPAD * EMB];    // agg1 fp16
__device__ uint16_t g_hh[(size_t)NPAD * HID];     // h fp16
__device__ uint16_t g_yh[(size_t)NPAD * EMB];     // y = h@W2rel fp16
__device__ uint16_t g_w1h[256 * 256];             // [n][k] fp16
__device__ uint16_t g_w2h[256 * 256];
// CSR structures
__device__ int  g_cnt[NPAD];
__device__ int  g_off[NPAD];
__device__ int  g_rank[E_EDGES];                  // rank of edge within its dst
__device__ int  g_bsum[NB1];
__device__ int2 g_edge[E_EDGES];    // {src, weight_bits} sorted by dst

// ---------------- helpers ----------------
__device__ __forceinline__ uint32_t smem_u32(const void* p) {
    uint32_t a;
    asm("{ .reg .u64 t; cvta.to.shared.u64 t, %1; cvt.u32.u64 %0, t; }" : "=r"(a) : "l"(p));
    return a;
}
#define LDSM_X4(r0, r1, r2, r3, addr) \
    asm volatile("ldmatrix.sync.aligned.m8n8.x4.shared.b16 {%0,%1,%2,%3}, [%4];" \
        : "=r"(r0), "=r"(r1), "=r"(r2), "=r"(r3) : "r"(addr))
#define MMA_F16(c, a, b0, b1) \
    asm volatile("mma.sync.aligned.m16n8k16.row.col.f32.f16.f16.f32 " \
        "{%0,%1,%2,%3}, {%4,%5,%6,%7}, {%8,%9}, {%0,%1,%2,%3};" \
        : "+f"((c)[0]), "+f"((c)[1]), "+f"((c)[2]), "+f"((c)[3]) \
        : "r"((a)[0]), "r"((a)[1]), "r"((a)[2]), "r"((a)[3]), "r"(b0), "r"(b1))
#define CP16(dst, src) \
    asm volatile("cp.async.cg.shared.global [%0], [%1], 16;" :: "r"(dst), "l"(src))
#define CP_COMMIT() asm volatile("cp.async.commit_group;" ::: "memory")
template <int N> __device__ __forceinline__ void cp_wait() {
    asm volatile("cp.async.wait_group %0;" :: "n"(N) : "memory");
}
__device__ __forceinline__ uint32_t pack_h2(float a, float b) {
    __half2 t = __floats2half2_rn(a, b);
    return *reinterpret_cast<uint32_t*>(&t);
}
__device__ __forceinline__ uint2 pack_h4(float4 v) {
    return make_uint2(pack_h2(v.x, v.y), pack_h2(v.z, v.w));
}
__device__ __forceinline__ float4 unpack_h4(uint2 p) {
    float2 a = __half22float2(*reinterpret_cast<__half2*>(&p.x));
    float2 b = __half22float2(*reinterpret_cast<__half2*>(&p.y));
    return make_float4(a.x, a.y, b.x, b.y);
}

// ---------------- fused prep: build_x fp16 | weight fp16 + zero g_cnt ----------------
#define BX_BLOCKS 15000   // NN*32/256
__global__ __launch_bounds__(256)
void prep_kernel(const float* __restrict__ pol, const int* __restrict__ sid,
                 const float* __restrict__ Wp, const float* __restrict__ bp,
                 const float* __restrict__ semb, const float* __restrict__ tick,
                 const float* __restrict__ W1rel, const float* __restrict__ W1root,
                 const float* __restrict__ W2rel, const float* __restrict__ W2root)
{
    if (blockIdx.x < BX_BLOCKS) {
        int t = blockIdx.x * 256 + threadIdx.x;
        int node = t >> 5;
        int c4 = (t & 31) * 4;
        if (node >= NN) return;
        float4 r;
        if (node < N_POL) {
            float4 acc = *(const float4*)(bp + c4);
            #pragma unroll
            for (int k = 0; k < POL_FEAT; k++) {
                float f = __ldg(pol + node * POL_FEAT + k);
                float4 w = *(const float4*)(Wp + k * EMB + c4);
                acc.x += f * w.x; acc.y += f * w.y; acc.z += f * w.z; acc.w += f * w.w;
            }
            int s = sid[node];
            float4 se = *(const float4*)(semb + (size_t)s * EMB + c4);
            r.x = fmaxf(acc.x, 0.f) + se.x;
            r.y = fmaxf(acc.y, 0.f) + se.y;
            r.z = fmaxf(acc.z, 0.f) + se.z;
            r.w = fmaxf(acc.w, 0.f) + se.w;
        } else {
            r = *(const float4*)(tick + (size_t)(node - N_POL) * EMB + c4);
        }
        *(uint2*)&g_xh[(size_t)node * EMB + c4] = pack_h4(r);
    } else {
        int idx = (blockIdx.x - BX_BLOCKS) * 256 + threadIdx.x;   // 0..131071
        if (idx < NPAD / 4) ((int4*)g_cnt)[idx] = make_int4(0, 0, 0, 0);
        int which = idx >> 16;
        int e = idx & 65535;
        int n = e >> 8, k = e & 255;
        float v;
        if (which == 0) v = (k < 128) ? W1rel[k * 256 + n] : W1root[(k - 128) * 256 + n];
        else            v = (n < 128) ? W2rel[k * 128 + n] : W2root[k * 128 + (n - 128)];
        __half bh = __float2half(v);
        uint16_t h = *reinterpret_cast<uint16_t*>(&bh);
        if (which == 0) g_w1h[e] = h;
        else            g_w2h[e] = h;
    }
}

// ---------------- CSR build ----------------
// hist: count + record each edge's rank within its dst (uses the same atomic)
__global__ __launch_bounds__(256)
void hist_kernel(const int* __restrict__ ei)
{
    int e = blockIdx.x * 256 + threadIdx.x;
    if (e < E_EDGES) {
        int d = ei[E_EDGES + e];
        g_rank[e] = atomicAdd(&g_cnt[d], 1);
    }
}

__global__ __launch_bounds__(256)
void scan1_kernel()
{
    __shared__ int s[256];
    int tid = threadIdx.x;
    int idx = blockIdx.x * 256 + tid;
    int v = g_cnt[idx];
    s[tid] = v;
    __syncthreads();
    #pragma unroll
    for (int d = 1; d < 256; d <<= 1) {
        int t = (tid >= d) ? s[tid - d] : 0;
        __syncthreads();
        s[tid] += t;
        __syncthreads();
    }
    g_off[idx] = s[tid] - v;
    if (tid == 255) g_bsum[blockIdx.x] = s[255];
}

// fused scan2+scan3: each block reduces bsum[0..bid) and applies base
__global__ __launch_bounds__(256)
void scan23_kernel()
{
    __shared__ int sh[256];
    int tid = threadIdx.x;
    int bid = blockIdx.x;
    int part = 0;
    for (int j = tid; j < bid; j += 256) part += g_bsum[j];
    sh[tid] = part;
    __syncthreads();
    #pragma unroll
    for (int d = 128; d > 0; d >>= 1) {
        if (tid < d) sh[tid] += sh[tid + d];
        __syncthreads();
    }
    int base = sh[0];
    int idx = bid * 256 + tid;
    g_off[idx] += base;
}

// place: atomic-free — pos = off[dst] + rank[e]
__global__ __launch_bounds__(256)
void place_kernel(const int* __restrict__ ei, const float* __restrict__ ew)
{
    int e = blockIdx.x * 256 + threadIdx.x;
    if (e >= E_EDGES) return;
    int s = ei[e];
    int d = ei[E_EDGES + e];
    float w = ew[e];
    int pos = __ldg(&g_off[d]) + g_rank[e];
    g_edge[pos] = make_int2(s, __float_as_int(w));
}

// ---------------- gather1: a1 = fp16( sum_e w * x[src] ), 4-way unroll ----------------
__global__ __launch_bounds__(256)
void gather1_kernel()
{
    int t = blockIdx.x * blockDim.x + threadIdx.x;
    int node = t >> 5;
    int c4 = (t & 31) * 4;
    if (node >= NN) return;

    int cnt = __ldg(&g_cnt[node]);
    int off = __ldg(&g_off[node]);

    float4 acc = make_float4(0.f, 0.f, 0.f, 0.f);
    int i = 0;
    for (; i + 3 < cnt; i += 4) {
        int2 e0 = __ldg(&g_edge[off + i]);
        int2 e1 = __ldg(&g_edge[off + i + 1]);
        int2 e2 = __ldg(&g_edge[off + i + 2]);
        int2 e3 = __ldg(&g_edge[off + i + 3]);
        float4 v0 = unpack_h4(*(const uint2*)&g_xh[(size_t)e0.x * EMB + c4]);
        float4 v1 = unpack_h4(*(const uint2*)&g_xh[(size_t)e1.x * EMB + c4]);
        float4 v2 = unpack_h4(*(const uint2*)&g_xh[(size_t)e2.x * EMB + c4]);
        float4 v3 = unpack_h4(*(const uint2*)&g_xh[(size_t)e3.x * EMB + c4]);
        float w0 = __int_as_float(e0.y), w1 = __int_as_float(e1.y);
        float w2 = __int_as_float(e2.y), w3 = __int_as_float(e3.y);
        acc.x += w0 * v0.x + w1 * v1.x + w2 * v2.x + w3 * v3.x;
        acc.y += w0 * v0.y + w1 * v1.y + w2 * v2.y + w3 * v3.y;
        acc.z += w0 * v0.z + w1 * v1.z + w2 * v2.z + w3 * v3.z;
        acc.w += w0 * v0.w + w1 * v1.w + w2 * v2.w + w3 * v3.w;
    }
    for (; i < cnt; i++) {
        int2 e0 = __ldg(&g_edge[off + i]);
        float4 v0 = unpack_h4(*(const uint2*)&g_xh[(size_t)e0.x * EMB + c4]);
        float w0 = __int_as_float(e0.y);
        acc.x += w0 * v0.x; acc.y += w0 * v0.y;
        acc.z += w0 * v0.z; acc.w += w0 * v0.w;
    }

    *(uint2*)&g_a1h[(size_t)node * EMB + c4] = pack_h4(acc);
}

// ---------------- gather2: out += sum_e w * y[src]  (y fp16), 4-way unroll ----------------
__global__ __launch_bounds__(256)
void gather2_kernel(float* __restrict__ out)
{
    int t = blockIdx.x * blockDim.x + threadIdx.x;
    int node = t >> 5;
    int c4 = (t & 31) * 4;
    if (node >= NN) return;

    int cnt = __ldg(&g_cnt[node]);
    if (cnt == 0) return;
    int off = __ldg(&g_off[node]);

    float4 acc = make_float4(0.f, 0.f, 0.f, 0.f);
    int i = 0;
    for (; i + 3 < cnt; i += 4) {
        int2 e0 = __ldg(&g_edge[off + i]);
        int2 e1 = __ldg(&g_edge[off + i + 1]);
        int2 e2 = __ldg(&g_edge[off + i + 2]);
        int2 e3 = __ldg(&g_edge[off + i + 3]);
        float4 v0 = unpack_h4(*(const uint2*)&g_yh[(size_t)e0.x * EMB + c4]);
        float4 v1 = unpack_h4(*(const uint2*)&g_yh[(size_t)e1.x * EMB + c4]);
        float4 v2 = unpack_h4(*(const uint2*)&g_yh[(size_t)e2.x * EMB + c4]);
        float4 v3 = unpack_h4(*(const uint2*)&g_yh[(size_t)e3.x * EMB + c4]);
        float w0 = __int_as_float(e0.y), w1 = __int_as_float(e1.y);
        float w2 = __int_as_float(e2.y), w3 = __int_as_float(e3.y);
        acc.x += w0 * v0.x + w1 * v1.x + w2 * v2.x + w3 * v3.x;
        acc.y += w0 * v0.y + w1 * v1.y + w2 * v2.y + w3 * v3.y;
        acc.z += w0 * v0.z + w1 * v1.z + w2 * v2.z + w3 * v3.z;
        acc.w += w0 * v0.w + w1 * v1.w + w2 * v2.w + w3 * v3.w;
    }
    for (; i < cnt; i++) {
        int2 e0 = __ldg(&g_edge[off + i]);
        float4 v0 = unpack_h4(*(const uint2*)&g_yh[(size_t)e0.x * EMB + c4]);
        float w0 = __int_as_float(e0.y);
        acc.x += w0 * v0.x; acc.y += w0 * v0.y;
        acc.z += w0 * v0.z; acc.w += w0 * v0.w;
    }

    float* o = out + (size_t)node * EMB + c4;
    float4 cur = *(float4*)o;
    cur.x += acc.x; cur.y += acc.y; cur.z += acc.z; cur.w += acc.w;
    *(float4*)o = cur;
}

// =========== persistent-B HMMA fp16 GEMM, BK=64 (4 chunks), per-tile pipeline (R12) ===========
// MODE 1: A = [a1|x] fp16, writes g_hh = fp16(relu(acc + b1))
// MODE 2: A = h fp16, writes y fp16 | out f32 (+b2)
#define A_KSTR  72                        // 64 + 8 pad fp16
#define A_PLANE (128 * A_KSTR * 2)        // 18432
#define B_KSTR  264
#define B_PLANE (64 * B_KSTR * 2)         // 33792
#define SM_A    (B_PLANE)
#define SMTOT   (SM_A + 2 * A_PLANE)      // 70656
#define NSLOT   111                       // 444 CTAs / 4 quarters (3 per SM)

template <int MODE>
__global__ __launch_bounds__(256, 3)
void gcn_gemm_mma(const float* __restrict__ bias, float* __restrict__ dout)
{
    extern __shared__ char smem[];
    const uint32_t sb = smem_u32(smem);

    const int tid  = threadIdx.x;
    const int lane = tid & 31;
    const int wid  = tid >> 5;
    const int wm   = wid >> 1;
    const int wn   = wid & 1;
    const int q    = blockIdx.x & 3;
    const int slot = blockIdx.x >> 2;

    const uint16_t* wh = (MODE == 1) ? g_w1h : g_w2h;

    // ---- load B quarter once: [64 n][256 k]
    #pragma unroll
    for (int i = 0; i < 8; i++) {
        int c = i * 256 + tid;
        int row = c >> 5;
        int col = c & 31;
        const uint16_t* src = wh + (size_t)(q * 64 + row) * 256 + col * 8;
        uint32_t dst = sb + (uint32_t)(row * B_KSTR + col * 8) * 2;
        CP16(dst, src);
    }
    CP_COMMIT();
    cp_wait<0>();
    __syncthreads();

    auto issue = [&](int m0, int kc, int st) {
        const uint16_t* ah;
        int astr, kb;
        if (MODE == 1) {
            ah = (kc < 2) ? g_a1h : g_xh;
            astr = 128; kb = (kc & 1) * 64;
        } else {
            ah = g_hh; astr = 256; kb = kc * 64;
        }
        uint32_t base = sb + SM_A + st * A_PLANE;
        #pragma unroll
        for (int i = 0; i < 4; i++) {
            int c = i * 256 + tid;
            int row = c >> 3;
            int col = c & 7;
            const uint16_t* src = ah + (size_t)(m0 + row) * astr + kb + col * 8;
            uint32_t dst = base + (uint32_t)(row * A_KSTR + col * 8) * 2;
            CP16(dst, src);
        }
        CP_COMMIT();
    };

    const int rA = (lane & 7) + ((lane >> 3) & 1) * 8;
    const int kA = (lane >> 4) * 8;
    const int rB = (lane & 7) + ((lane >> 4) & 1) * 8;
    const int kB = ((lane >> 3) & 1) * 8;
    const int rr = lane >> 2;
    const int cc = (lane & 3) * 2;

    for (int t = slot; t < NT; t += NSLOT) {
        const int m0 = t * 128;

        float acc[2][4][4];
        #pragma unroll
        for (int i = 0; i < 2; i++)
            #pragma unroll
            for (int j = 0; j < 4; j++)
                #pragma unroll
                for (int p = 0; p < 4; p++) acc[i][j][p] = 0.f;

        issue(m0, 0, 0);

        for (int kc = 0; kc < 4; kc++) {
            cp_wait<0>();              // stage kc data landed
            __syncthreads();           // publish + protect other stage before reuse
            if (kc + 1 < 4) issue(m0, kc + 1, (kc + 1) & 1);

            uint32_t uA = sb + SM_A + (kc & 1) * A_PLANE;

            #pragma unroll
            for (int ks = 0; ks < 4; ks++) {
                uint32_t ah[2][4];
                #pragma unroll
                for (int mt = 0; mt < 2; mt++) {
                    uint32_t off = ((uint32_t)((wm * 32 + mt * 16 + rA) * A_KSTR + ks * 16 + kA)) * 2;
                    LDSM_X4(ah[mt][0], ah[mt][1], ah[mt][2], ah[mt][3], uA + off);
                }
                #pragma unroll
                for (int np = 0; np < 2; np++) {
                    uint32_t boff = ((uint32_t)((wn * 32 + np * 16 + rB) * B_KSTR + kc * 64 + ks * 16 + kB)) * 2;
                    uint32_t bh[4];
                    LDSM_X4(bh[0], bh[1], bh[2], bh[3], sb + boff);
                    #pragma unroll
                    for (int mt = 0; mt < 2; mt++) {
                        MMA_F16(acc[mt][np * 2 + 0], ah[mt], bh[0], bh[1]);
                        MMA_F16(acc[mt][np * 2 + 1], ah[mt], bh[2], bh[3]);
                    }
                }
            }
            __syncthreads();           // reads of stage kc done before reuse at kc+2
        }

        #pragma unroll
        for (int mt = 0; mt < 2; mt++) {
            #pragma unroll
            for (int j = 0; j < 4; j++) {
                int gm = m0 + wm * 32 + mt * 16 + rr;
                int gN = q * 64 + wn * 32 + j * 8 + cc;
                if (MODE == 1) {
                    float2 bv = *(const float2*)(bias + gN);
                    float v00 = fmaxf(acc[mt][j][0] + bv.x, 0.f);
                    float v01 = fmaxf(acc[mt][j][1] + bv.y, 0.f);
                    float v10 = fmaxf(acc[mt][j][2] + bv.x, 0.f);
                    float v11 = fmaxf(acc[mt][j][3] + bv.y, 0.f);
                    *(uint32_t*)&g_hh[(size_t)gm * 256 + gN]       = pack_h2(v00, v01);
                    *(uint32_t*)&g_hh[(size_t)(gm + 8) * 256 + gN] = pack_h2(v10, v11);
                } else if (gN < 128) {
                    *(uint32_t*)&g_yh[(size_t)gm * 128 + gN]       = pack_h2(acc[mt][j][0], acc[mt][j][1]);
                    *(uint32_t*)&g_yh[(size_t)(gm + 8) * 128 + gN] = pack_h2(acc[mt][j][2], acc[mt][j][3]);
                } else {
                    int nc = gN - 128;
                    float2 bv = *(const float2*)(bias + nc);
                    if (gm < NN)
                        *(float2*)(dout + (size_t)gm * 128 + nc) =
                            make_float2(acc[mt][j][0] + bv.x, acc[mt][j][1] + bv.y);
                    if (gm + 8 < NN)
                        *(float2*)(dout + (size_t)(gm + 8) * 128 + nc) =
                            make_float2(acc[mt][j][2] + bv.x, acc[mt][j][3] + bv.y);
                }
            }
        }
    }
}

// ---------------- launch ----------------
extern "C" void kernel_launch(void* const* d_in, const int* in_sizes, int n_in,
                              void* d_out, int out_size)
{
    const float* pol   = (const float*)d_in[0];
    const int*   sid   = (const int*)  d_in[1];
    const int*   ei    = (const int*)  d_in[2];
    const float* ew    = (const float*)d_in[3];
    const float* Wp    = (const float*)d_in[4];
    const float* bp    = (const float*)d_in[5];
    const float* semb  = (const float*)d_in[6];
    const float* tick  = (const float*)d_in[7];
    const float* W1rel = (const float*)d_in[8];
    const float* b1    = (const float*)d_in[9];
    const float* W1root= (const float*)d_in[10];
    const float* W2rel = (const float*)d_in[11];
    const float* b2    = (const float*)d_in[12];
    const float* W2root= (const float*)d_in[13];
    float* out = (float*)d_out;

    cudaFuncSetAttribute(gcn_gemm_mma<1>, cudaFuncAttributeMaxDynamicSharedMemorySize, SMTOT);
    cudaFuncSetAttribute(gcn_gemm_mma<2>, cudaFuncAttributeMaxDynamicSharedMemorySize, SMTOT);

    // 0) fused prep: x fp16 | W fp16 + zero g_cnt
    prep_kernel<<<BX_BLOCKS + 512, 256>>>(pol, sid, Wp, bp, semb, tick,
                                          W1rel, W1root, W2rel, W2root);
    // 1) CSR build
    hist_kernel<<<(E_EDGES + 255) / 256, 256>>>(ei);
    scan1_kernel<<<NB1, 256>>>();
    scan23_kernel<<<NB1, 256>>>();
    place_kernel<<<(E_EDGES + 255) / 256, 256>>>(ei, ew);
    // 2) gather1
    gather1_kernel<<<NN * 32 / 256, 256>>>();
    // 3) GEMM1
    gcn_gemm_mma<1><<<4 * NSLOT, 256, SMTOT>>>(b1, nullptr);
    // 4) GEMM2
    gcn_gemm_mma<2><<<4 * NSLOT, 256, SMTOT>>>(b2, out);
    // 5) gather2
    gather2_kernel<<<NN * 32 / 256, 256>>>(out);
}

// round 17
// speedup vs baseline: 1.1368x; 1.0049x over previous
#include <cuda_runtime.h>
#include <cuda_fp16.h>
#include <cstdint>

#define N_POL   100000
#define N_TICK  20000
#define NN      (N_POL + N_TICK)   // 120000
#define NPAD    120064
#define NB1     469
#define NT      938                // m-tiles of 128
#define E_EDGES 1000000
#define POL_FEAT 7
#define EMB     128
#define HID     256
#define OUTD    128

// ---------------- scratch (static device globals; no allocation) ----------------
__device__ uint16_t g_xh[(size_t)NPAD * EMB];     // x fp16
__device__ uint16_t g_a1h[(size_t)NPAD * EMB];    // agg1 fp16
__device__ uint16_t g_hh[(size_t)NPAD * HID];     // h fp16
__device__ uint16_t g_yh[(size_t)NPAD * EMB];     // y = h@W2rel fp16
__device__ uint16_t g_w1h[256 * 256];             // [n][k] fp16
__device__ uint16_t g_w2h[256 * 256];
// CSR structures
__device__ int  g_cnt[NPAD];
__device__ int  g_off[NPAD];
__device__ int  g_rank[E_EDGES];                  // rank of edge within its dst
__device__ int  g_total;                          // atomic base partition counter
__device__ int2 g_edge[E_EDGES];    // {src, weight_bits} grouped by dst

// ---------------- helpers ----------------
__device__ __forceinline__ uint32_t smem_u32(const void* p) {
    uint32_t a;
    asm("{ .reg .u64 t; cvta.to.shared.u64 t, %1; cvt.u32.u64 %0, t; }" : "=r"(a) : "l"(p));
    return a;
}
#define LDSM_X4(r0, r1, r2, r3, addr) \
    asm volatile("ldmatrix.sync.aligned.m8n8.x4.shared.b16 {%0,%1,%2,%3}, [%4];" \
        : "=r"(r0), "=r"(r1), "=r"(r2), "=r"(r3) : "r"(addr))
#define MMA_F16(c, a, b0, b1) \
    asm volatile("mma.sync.aligned.m16n8k16.row.col.f32.f16.f16.f32 " \
        "{%0,%1,%2,%3}, {%4,%5,%6,%7}, {%8,%9}, {%0,%1,%2,%3};" \
        : "+f"((c)[0]), "+f"((c)[1]), "+f"((c)[2]), "+f"((c)[3]) \
        : "r"((a)[0]), "r"((a)[1]), "r"((a)[2]), "r"((a)[3]), "r"(b0), "r"(b1))
#define CP16(dst, src) \
    asm volatile("cp.async.cg.shared.global [%0], [%1], 16;" :: "r"(dst), "l"(src))
#define CP_COMMIT() asm volatile("cp.async.commit_group;" ::: "memory")
template <int N> __device__ __forceinline__ void cp_wait() {
    asm volatile("cp.async.wait_group %0;" :: "n"(N) : "memory");
}
__device__ __forceinline__ uint32_t pack_h2(float a, float b) {
    __half2 t = __floats2half2_rn(a, b);
    return *reinterpret_cast<uint32_t*>(&t);
}
__device__ __forceinline__ uint2 pack_h4(float4 v) {
    return make_uint2(pack_h2(v.x, v.y), pack_h2(v.z, v.w));
}
__device__ __forceinline__ float4 unpack_h4(uint2 p) {
    float2 a = __half22float2(*reinterpret_cast<__half2*>(&p.x));
    float2 b = __half22float2(*reinterpret_cast<__half2*>(&p.y));
    return make_float4(a.x, a.y, b.x, b.y);
}

// ---------------- fused prep: build_x fp16 | weight fp16 + zero g_cnt/g_total ----------------
#define BX_BLOCKS 15000   // NN*32/256
__global__ __launch_bounds__(256)
void prep_kernel(const float* __restrict__ pol, const int* __restrict__ sid,
                 const float* __restrict__ Wp, const float* __restrict__ bp,
                 const float* __restrict__ semb, const float* __restrict__ tick,
                 const float* __restrict__ W1rel, const float* __restrict__ W1root,
                 const float* __restrict__ W2rel, const float* __restrict__ W2root)
{
    if (blockIdx.x < BX_BLOCKS) {
        int t = blockIdx.x * 256 + threadIdx.x;
        int node = t >> 5;
        int c4 = (t & 31) * 4;
        if (node >= NN) return;
        float4 r;
        if (node < N_POL) {
            float4 acc = *(const float4*)(bp + c4);
            #pragma unroll
            for (int k = 0; k < POL_FEAT; k++) {
                float f = __ldg(pol + node * POL_FEAT + k);
                float4 w = *(const float4*)(Wp + k * EMB + c4);
                acc.x += f * w.x; acc.y += f * w.y; acc.z += f * w.z; acc.w += f * w.w;
            }
            int s = sid[node];
            float4 se = *(const float4*)(semb + (size_t)s * EMB + c4);
            r.x = fmaxf(acc.x, 0.f) + se.x;
            r.y = fmaxf(acc.y, 0.f) + se.y;
            r.z = fmaxf(acc.z, 0.f) + se.z;
            r.w = fmaxf(acc.w, 0.f) + se.w;
        } else {
            r = *(const float4*)(tick + (size_t)(node - N_POL) * EMB + c4);
        }
        *(uint2*)&g_xh[(size_t)node * EMB + c4] = pack_h4(r);
    } else {
        int idx = (blockIdx.x - BX_BLOCKS) * 256 + threadIdx.x;   // 0..131071
        if (idx < NPAD / 4) ((int4*)g_cnt)[idx] = make_int4(0, 0, 0, 0);
        if (idx == 0) g_total = 0;
        int which = idx >> 16;
        int e = idx & 65535;
        int n = e >> 8, k = e & 255;
        float v;
        if (which == 0) v = (k < 128) ? W1rel[k * 256 + n] : W1root[(k - 128) * 256 + n];
        else            v = (n < 128) ? W2rel[k * 128 + n] : W2root[k * 128 + (n - 128)];
        __half bh = __float2half(v);
        uint16_t h = *reinterpret_cast<uint16_t*>(&bh);
        if (which == 0) g_w1h[e] = h;
        else            g_w2h[e] = h;
    }
}

// ---------------- CSR build ----------------
// hist: count + record each edge's rank within its dst (uses the same atomic)
__global__ __launch_bounds__(256)
void hist_kernel(const int* __restrict__ ei)
{
    int e = blockIdx.x * 256 + threadIdx.x;
    if (e < E_EDGES) {
        int d = ei[E_EDGES + e];
        g_rank[e] = atomicAdd(&g_cnt[d], 1);
    }
}

// single-pass scan: local block scan + atomic base partition.
// Ordering across blocks is arbitrary (valid: gathers only need disjoint,
// correctly-sized per-node ranges; within-node order fixed by g_rank).
__global__ __launch_bounds__(256)
void scan_kernel()
{
    __shared__ int s[256];
    __shared__ int s_base;
    int tid = threadIdx.x;
    int idx = blockIdx.x * 256 + tid;
    int v = g_cnt[idx];
    s[tid] = v;
    __syncthreads();
    #pragma unroll
    for (int d = 1; d < 256; d <<= 1) {
        int t = (tid >= d) ? s[tid - d] : 0;
        __syncthreads();
        s[tid] += t;
        __syncthreads();
    }
    if (tid == 255) s_base = atomicAdd(&g_total, s[255]);
    __syncthreads();
    g_off[idx] = s_base + s[tid] - v;
}

// place: atomic-free — pos = off[dst] + rank[e]
__global__ __launch_bounds__(256)
void place_kernel(const int* __restrict__ ei, const float* __restrict__ ew)
{
    int e = blockIdx.x * 256 + threadIdx.x;
    if (e >= E_EDGES) return;
    int s = ei[e];
    int d = ei[E_EDGES + e];
    float w = ew[e];
    int pos = __ldg(&g_off[d]) + g_rank[e];
    g_edge[pos] = make_int2(s, __float_as_int(w));
}

// ---------------- gather1: a1 = fp16( sum_e w * x[src] ), 4-way unroll ----------------
__global__ __launch_bounds__(256)
void gather1_kernel()
{
    int t = blockIdx.x * blockDim.x + threadIdx.x;
    int node = t >> 5;
    int c4 = (t & 31) * 4;
    if (node >= NN) return;

    int cnt = __ldg(&g_cnt[node]);
    int off = __ldg(&g_off[node]);

    float4 acc = make_float4(0.f, 0.f, 0.f, 0.f);
    int i = 0;
    for (; i + 3 < cnt; i += 4) {
        int2 e0 = __ldg(&g_edge[off + i]);
        int2 e1 = __ldg(&g_edge[off + i + 1]);
        int2 e2 = __ldg(&g_edge[off + i + 2]);
        int2 e3 = __ldg(&g_edge[off + i + 3]);
        float4 v0 = unpack_h4(*(const uint2*)&g_xh[(size_t)e0.x * EMB + c4]);
        float4 v1 = unpack_h4(*(const uint2*)&g_xh[(size_t)e1.x * EMB + c4]);
        float4 v2 = unpack_h4(*(const uint2*)&g_xh[(size_t)e2.x * EMB + c4]);
        float4 v3 = unpack_h4(*(const uint2*)&g_xh[(size_t)e3.x * EMB + c4]);
        float w0 = __int_as_float(e0.y), w1 = __int_as_float(e1.y);
        float w2 = __int_as_float(e2.y), w3 = __int_as_float(e3.y);
        acc.x += w0 * v0.x + w1 * v1.x + w2 * v2.x + w3 * v3.x;
        acc.y += w0 * v0.y + w1 * v1.y + w2 * v2.y + w3 * v3.y;
        acc.z += w0 * v0.z + w1 * v1.z + w2 * v2.z + w3 * v3.z;
        acc.w += w0 * v0.w + w1 * v1.w + w2 * v2.w + w3 * v3.w;
    }
    for (; i < cnt; i++) {
        int2 e0 = __ldg(&g_edge[off + i]);
        float4 v0 = unpack_h4(*(const uint2*)&g_xh[(size_t)e0.x * EMB + c4]);
        float w0 = __int_as_float(e0.y);
        acc.x += w0 * v0.x; acc.y += w0 * v0.y;
        acc.z += w0 * v0.z; acc.w += w0 * v0.w;
    }

    *(uint2*)&g_a1h[(size_t)node * EMB + c4] = pack_h4(acc);
}

// ---------------- gather2: out += sum_e w * y[src]  (y fp16), 4-way unroll ----------------
__global__ __launch_bounds__(256)
void gather2_kernel(float* __restrict__ out)
{
    int t = blockIdx.x * blockDim.x + threadIdx.x;
    int node = t >> 5;
    int c4 = (t & 31) * 4;
    if (node >= NN) return;

    int cnt = __ldg(&g_cnt[node]);
    if (cnt == 0) return;
    int off = __ldg(&g_off[node]);

    float4 acc = make_float4(0.f, 0.f, 0.f, 0.f);
    int i = 0;
    for (; i + 3 < cnt; i += 4) {
        int2 e0 = __ldg(&g_edge[off + i]);
        int2 e1 = __ldg(&g_edge[off + i + 1]);
        int2 e2 = __ldg(&g_edge[off + i + 2]);
        int2 e3 = __ldg(&g_edge[off + i + 3]);
        float4 v0 = unpack_h4(*(const uint2*)&g_yh[(size_t)e0.x * EMB + c4]);
        float4 v1 = unpack_h4(*(const uint2*)&g_yh[(size_t)e1.x * EMB + c4]);
        float4 v2 = unpack_h4(*(const uint2*)&g_yh[(size_t)e2.x * EMB + c4]);
        float4 v3 = unpack_h4(*(const uint2*)&g_yh[(size_t)e3.x * EMB + c4]);
        float w0 = __int_as_float(e0.y), w1 = __int_as_float(e1.y);
        float w2 = __int_as_float(e2.y), w3 = __int_as_float(e3.y);
        acc.x += w0 * v0.x + w1 * v1.x + w2 * v2.x + w3 * v3.x;
        acc.y += w0 * v0.y + w1 * v1.y + w2 * v2.y + w3 * v3.y;
        acc.z += w0 * v0.z + w1 * v1.z + w2 * v2.z + w3 * v3.z;
        acc.w += w0 * v0.w + w1 * v1.w + w2 * v2.w + w3 * v3.w;
    }
    for (; i < cnt; i++) {
        int2 e0 = __ldg(&g_edge[off + i]);
        float4 v0 = unpack_h4(*(const uint2*)&g_yh[(size_t)e0.x * EMB + c4]);
        float w0 = __int_as_float(e0.y);
        acc.x += w0 * v0.x; acc.y += w0 * v0.y;
        acc.z += w0 * v0.z; acc.w += w0 * v0.w;
    }

    float* o = out + (size_t)node * EMB + c4;
    float4 cur = *(float4*)o;
    cur.x += acc.x; cur.y += acc.y; cur.z += acc.z; cur.w += acc.w;
    *(float4*)o = cur;
}

// =========== persistent-B HMMA fp16 GEMM, BK=64 (4 chunks), reduced barriers ===========
// MODE 1: A = [a1|x] fp16, writes g_hh = fp16(relu(acc + b1))
// MODE 2: A = h fp16, writes y fp16 | out f32 (+b2)
#define A_KSTR  72                        // 64 + 8 pad fp16
#define A_PLANE (128 * A_KSTR * 2)        // 18432
#define B_KSTR  264
#define B_PLANE (64 * B_KSTR * 2)         // 33792
#define SM_A    (B_PLANE)
#define SMTOT   (SM_A + 2 * A_PLANE)      // 70656
#define NSLOT   111                       // 444 CTAs / 4 quarters (3 per SM)

template <int MODE>
__global__ __launch_bounds__(256, 3)
void gcn_gemm_mma(const float* __restrict__ bias, float* __restrict__ dout)
{
    extern __shared__ char smem[];
    const uint32_t sb = smem_u32(smem);

    const int tid  = threadIdx.x;
    const int lane = tid & 31;
    const int wid  = tid >> 5;
    const int wm   = wid >> 1;
    const int wn   = wid & 1;
    const int q    = blockIdx.x & 3;
    const int slot = blockIdx.x >> 2;

    const uint16_t* wh = (MODE == 1) ? g_w1h : g_w2h;

    // ---- load B quarter once: [64 n][256 k]
    #pragma unroll
    for (int i = 0; i < 8; i++) {
        int c = i * 256 + tid;
        int row = c >> 5;
        int col = c & 31;
        const uint16_t* src = wh + (size_t)(q * 64 + row) * 256 + col * 8;
        uint32_t dst = sb + (uint32_t)(row * B_KSTR + col * 8) * 2;
        CP16(dst, src);
    }
    CP_COMMIT();
    cp_wait<0>();
    __syncthreads();

    auto issue = [&](int m0, int kc, int st) {
        const uint16_t* ah;
        int astr, kb;
        if (MODE == 1) {
            ah = (kc < 2) ? g_a1h : g_xh;
            astr = 128; kb = (kc & 1) * 64;
        } else {
            ah = g_hh; astr = 256; kb = kc * 64;
        }
        uint32_t base = sb + SM_A + st * A_PLANE;
        #pragma unroll
        for (int i = 0; i < 4; i++) {
            int c = i * 256 + tid;
            int row = c >> 3;
            int col = c & 7;
            const uint16_t* src = ah + (size_t)(m0 + row) * astr + kb + col * 8;
            uint32_t dst = base + (uint32_t)(row * A_KSTR + col * 8) * 2;
            CP16(dst, src);
        }
        CP_COMMIT();
    };

    const int rA = (lane & 7) + ((lane >> 3) & 1) * 8;
    const int kA = (lane >> 4) * 8;
    const int rB = (lane & 7) + ((lane >> 4) & 1) * 8;
    const int kB = ((lane >> 3) & 1) * 8;
    const int rr = lane >> 2;
    const int cc = (lane & 3) * 2;

    for (int t = slot; t < NT; t += NSLOT) {
        const int m0 = t * 128;

        float acc[2][4][4];
        #pragma unroll
        for (int i = 0; i < 2; i++)
            #pragma unroll
            for (int j = 0; j < 4; j++)
                #pragma unroll
                for (int p = 0; p < 4; p++) acc[i][j][p] = 0.f;

        issue(m0, 0, 0);

        for (int kc = 0; kc < 4; kc++) {
            cp_wait<0>();              // stage kc data landed (this thread's view)
            __syncthreads();           // publish stage kc to all warps; also orders
                                       // prior iteration's reads before this issue
            if (kc + 1 < 4) issue(m0, kc + 1, (kc + 1) & 1);

            uint32_t uA = sb + SM_A + (kc & 1) * A_PLANE;

            #pragma unroll
            for (int ks = 0; ks < 4; ks++) {
                uint32_t ah[2][4];
                #pragma unroll
                for (int mt = 0; mt < 2; mt++) {
                    uint32_t off = ((uint32_t)((wm * 32 + mt * 16 + rA) * A_KSTR + ks * 16 + kA)) * 2;
                    LDSM_X4(ah[mt][0], ah[mt][1], ah[mt][2], ah[mt][3], uA + off);
                }
                #pragma unroll
                for (int np = 0; np < 2; np++) {
                    uint32_t boff = ((uint32_t)((wn * 32 + np * 16 + rB) * B_KSTR + kc * 64 + ks * 16 + kB)) * 2;
                    uint32_t bh[4];
                    LDSM_X4(bh[0], bh[1], bh[2], bh[3], sb + boff);
                    #pragma unroll
                    for (int mt = 0; mt < 2; mt++) {
                        MMA_F16(acc[mt][np * 2 + 0], ah[mt], bh[0], bh[1]);
                        MMA_F16(acc[mt][np * 2 + 1], ah[mt], bh[2], bh[3]);
                    }
                }
            }
            // NOTE: no end-of-chunk barrier — the next iteration's entry barrier
            // (or the end-of-tile barrier below) orders these reads before the
            // stage's next overwrite.
        }
        __syncthreads();               // all reads done before next tile's issue(…, 0, 0)

        #pragma unroll
        for (int mt = 0; mt < 2; mt++) {
            #pragma unroll
            for (int j = 0; j < 4; j++) {
                int gm = m0 + wm * 32 + mt * 16 + rr;
                int gN = q * 64 + wn * 32 + j * 8 + cc;
                if (MODE == 1) {
                    float2 bv = *(const float2*)(bias + gN);
                    float v00 = fmaxf(acc[mt][j][0] + bv.x, 0.f);
                    float v01 = fmaxf(acc[mt][j][1] + bv.y, 0.f);
                    float v10 = fmaxf(acc[mt][j][2] + bv.x, 0.f);
                    float v11 = fmaxf(acc[mt][j][3] + bv.y, 0.f);
                    *(uint32_t*)&g_hh[(size_t)gm * 256 + gN]       = pack_h2(v00, v01);
                    *(uint32_t*)&g_hh[(size_t)(gm + 8) * 256 + gN] = pack_h2(v10, v11);
                } else if (gN < 128) {
                    *(uint32_t*)&g_yh[(size_t)gm * 128 + gN]       = pack_h2(acc[mt][j][0], acc[mt][j][1]);
                    *(uint32_t*)&g_yh[(size_t)(gm + 8) * 128 + gN] = pack_h2(acc[mt][j][2], acc[mt][j][3]);
                } else {
                    int nc = gN - 128;
                    float2 bv = *(const float2*)(bias + nc);
                    if (gm < NN)
                        *(float2*)(dout + (size_t)gm * 128 + nc) =
                            make_float2(acc[mt][j][0] + bv.x, acc[mt][j][1] + bv.y);
                    if (gm + 8 < NN)
                        *(float2*)(dout + (size_t)(gm + 8) * 128 + nc) =
                            make_float2(acc[mt][j][2] + bv.x, acc[mt][j][3] + bv.y);
                }
            }
        }
    }
}

// ---------------- launch ----------------
extern "C" void kernel_launch(void* const* d_in, const int* in_sizes, int n_in,
                              void* d_out, int out_size)
{
    const float* pol   = (const float*)d_in[0];
    const int*   sid   = (const int*)  d_in[1];
    const int*   ei    = (const int*)  d_in[2];
    const float* ew    = (const float*)d_in[3];
    const float* Wp    = (const float*)d_in[4];
    const float* bp    = (const float*)d_in[5];
    const float* semb  = (const float*)d_in[6];
    const float* tick  = (const float*)d_in[7];
    const float* W1rel = (const float*)d_in[8];
    const float* b1    = (const float*)d_in[9];
    const float* W1root= (const float*)d_in[10];
    const float* W2rel = (const float*)d_in[11];
    const float* b2    = (const float*)d_in[12];
    const float* W2root= (const float*)d_in[13];
    float* out = (float*)d_out;

    cudaFuncSetAttribute(gcn_gemm_mma<1>, cudaFuncAttributeMaxDynamicSharedMemorySize, SMTOT);
    cudaFuncSetAttribute(gcn_gemm_mma<2>, cudaFuncAttributeMaxDynamicSharedMemorySize, SMTOT);

    // 0) fused prep: x fp16 | W fp16 + zero g_cnt/g_total
    prep_kernel<<<BX_BLOCKS + 512, 256>>>(pol, sid, Wp, bp, semb, tick,
                                          W1rel, W1root, W2rel, W2root);
    // 1) CSR build
    hist_kernel<<<(E_EDGES + 255) / 256, 256>>>(ei);
    scan_kernel<<<NB1, 256>>>();
    place_kernel<<<(E_EDGES + 255) / 256, 256>>>(ei, ew);
    // 2) gather1
    gather1_kernel<<<NN * 32 / 256, 256>>>();
    // 3) GEMM1
    gcn_gemm_mma<1><<<4 * NSLOT, 256, SMTOT>>>(b1, nullptr);
    // 4) GEMM2
    gcn_gemm_mma<2><<<4 * NSLOT, 256, SMTOT>>>(b2, out);
    // 5) gather2
    gather2_kernel<<<NN * 32 / 256, 256>>>(out);
}